// round 11
// baseline (speedup 1.0000x reference)
#include <cuda_runtime.h>
#include <cuda_bf16.h>
#include <cstdint>

// FP4 codebook magnitudes {0, 0.5, 1, 1.5, 2, 3, 4, 6} == e2m1.
// RN-to-1-mantissa-bit via integer round for |q| in [0.875, 8):
//   rb = (bits + 0x00200000) & 0x7fc00000
// fmin(.,6) clamps top, fmax(.,1) fixes [0.75,0.875), two selects handle
// thresholds 0.25 / 0.75. Exact midpoints: measure zero (rel_err was 0.0).
__device__ __forceinline__ float quant_one(float x, float inv_s, float s) {
    float q = x * inv_s;
    unsigned u = __float_as_uint(q);
    unsigned rb = (u + 0x00200000u) & 0x7fc00000u;
    float r = fminf(__uint_as_float(rb), 6.0f);
    r = fmaxf(r, 1.0f);
    r = (fabsf(q) < 0.75f) ? 0.5f : r;
    r = (fabsf(q) < 0.25f) ? 0.0f : r;
    float m = __uint_as_float(__float_as_uint(r) | (u & 0x80000000u));
    return m * s;
}

__device__ __forceinline__ float4 quant_vec(float4 v, float inv_s, float s) {
    float4 r;
    r.x = quant_one(v.x, inv_s, s);
    r.y = quant_one(v.y, inv_s, s);
    r.z = quant_one(v.z, inv_s, s);
    r.w = quant_one(v.w, inv_s, s);
    return r;
}

__device__ __forceinline__ unsigned smem_u32(const void* p) {
    unsigned a;
    asm("{ .reg .u64 t; cvta.to.shared.u64 t, %1; cvt.u32.u64 %0, t; }"
        : "=r"(a) : "l"(p));
    return a;
}

// R11: async-bulk (TMA-class UBLKCP) read pipeline.
// One block = one 16KB row. tid0 issues ONE cp.async.bulk for the whole row;
// in-flight read data lives in SMEM (zero register cost -> full occupancy),
// warps sleep on an mbarrier instead of per-warp LDG scoreboards. 8 CTAs/SM
// keep 128KB of reads in flight continuously; LSU is dedicated to stores.
__global__ void __launch_bounds__(256) quantizer_fp4_kernel(
    const float4* __restrict__ x,
    const float*  __restrict__ scale,
    float4*       __restrict__ out)
{
    __shared__ __align__(128) float4 buf[1024];   // 16KB = one row
    __shared__ __align__(8) uint64_t mbar;

    const unsigned row  = blockIdx.x;             // 4096 rows
    const unsigned tid  = threadIdx.x;
    const unsigned base = row * 1024u + tid;

    const unsigned mb = smem_u32(&mbar);

    if (tid == 0) {
        asm volatile("mbarrier.init.shared.b64 [%0], 1;" :: "r"(mb) : "memory");
    }
    __syncthreads();

    if (tid == 0) {
        asm volatile("mbarrier.arrive.expect_tx.shared.b64 _, [%0], 16384;"
                     :: "r"(mb) : "memory");
        asm volatile(
            "cp.async.bulk.shared::cta.global.mbarrier::complete_tx::bytes "
            "[%0], [%1], 16384, [%2];"
            :: "r"(smem_u32(buf)), "l"(x + row * 1024u), "r"(mb) : "memory");
    }

    // Overlap the (L2-resident) scale load with the bulk read
    float s = __ldg(scale + row);
    float inv_s = __frcp_rn(s);

    // Wait for bulk completion (acquire orders subsequent LDS after TMA writes)
    {
        unsigned done;
        asm volatile(
            "{\n\t"
            ".reg .pred p;\n\t"
            "mbarrier.try_wait.parity.acquire.cta.shared::cta.b64 p, [%1], 0;\n\t"
            "selp.b32 %0, 1, 0, p;\n\t"
            "}" : "=r"(done) : "r"(mb) : "memory");
        if (!done) {
            asm volatile(
                "{\n\t"
                ".reg .pred P1;\n\t"
                "WL_%=:\n\t"
                "mbarrier.try_wait.parity.acquire.cta.shared::cta.b64 P1, [%0], 0, 0x989680;\n\t"
                "@P1 bra.uni WD_%=;\n\t"
                "bra.uni WL_%=;\n\t"
                "WD_%=:\n\t"
                "}" :: "r"(mb) : "memory");
        }
    }

    // Conflict-free LDS.128 reads, compute, streaming stores
    float4 v0 = buf[tid];
    float4 v1 = buf[tid + 256];
    float4 v2 = buf[tid + 512];
    float4 v3 = buf[tid + 768];

    __stcs(out + base,       quant_vec(v0, inv_s, s));
    __stcs(out + base + 256, quant_vec(v1, inv_s, s));
    __stcs(out + base + 512, quant_vec(v2, inv_s, s));
    __stcs(out + base + 768, quant_vec(v3, inv_s, s));
}

extern "C" void kernel_launch(void* const* d_in, const int* in_sizes, int n_in,
                              void* d_out, int out_size) {
    const float4* x     = (const float4*)d_in[0];   // 4096*4096 fp32
    const float*  scale = (const float*) d_in[1];   // 4096 fp32
    // d_in[2] = code (fixed FP4 codebook) — implemented via bit-trick rounding
    float4* out = (float4*)d_out;

    quantizer_fp4_kernel<<<4096, 256>>>(x, scale, out);
}

// round 12
// speedup vs baseline: 1.1145x; 1.1145x over previous
#include <cuda_runtime.h>
#include <cuda_bf16.h>
#include <cstdint>

// FP4 codebook magnitudes {0, 0.5, 1, 1.5, 2, 3, 4, 6} == e2m1.
// RN-to-1-mantissa-bit via integer round for |q| in [0.875, 8):
//   rb = (bits + 0x00200000) & 0x7fc00000
// fmin(.,6) clamps top, fmax(.,1) fixes [0.75,0.875), two selects handle
// thresholds 0.25 / 0.75. Exact midpoints: measure zero (rel_err was 0.0).
__device__ __forceinline__ float quant_one(float x, float inv_s, float s) {
    float q = x * inv_s;
    unsigned u = __float_as_uint(q);
    unsigned rb = (u + 0x00200000u) & 0x7fc00000u;
    float r = fminf(__uint_as_float(rb), 6.0f);
    r = fmaxf(r, 1.0f);
    r = (fabsf(q) < 0.75f) ? 0.5f : r;
    r = (fabsf(q) < 0.25f) ? 0.0f : r;
    float m = __uint_as_float(__float_as_uint(r) | (u & 0x80000000u));
    return m * s;
}

__device__ __forceinline__ float4 quant_vec(float4 v, float inv_s, float s) {
    float4 r;
    r.x = quant_one(v.x, inv_s, s);
    r.y = quant_one(v.y, inv_s, s);
    r.z = quant_one(v.z, inv_s, s);
    r.w = quant_one(v.w, inv_s, s);
    return r;
}

// R12: persistent single-wave grid. 1184 blocks = 148 SMs x 8 CTAs resident
// simultaneously -> exactly ONE wave, zero wave-transition cost
// (T_wave_trans ~2360cyc each) and no stranded partial wave. Each block
// grid-strides over rows with the proven R4 body: 4 front-batched LDG.128 +
// block-uniform scale load (MLP_p1 = 5), bit-trick quant, streaming stores.
#define PERSIST_BLOCKS 1184u

__global__ void __launch_bounds__(256) quantizer_fp4_kernel(
    const float4* __restrict__ x,
    const float*  __restrict__ scale,
    float4*       __restrict__ out)
{
    const unsigned tid = threadIdx.x;

    for (unsigned row = blockIdx.x; row < 4096u; row += PERSIST_BLOCKS) {
        const unsigned base = row * 1024u + tid;

        float4 v0 = x[base];
        float4 v1 = x[base + 256];
        float4 v2 = x[base + 512];
        float4 v3 = x[base + 768];
        float  s  = __ldg(scale + row);

        float inv_s = __frcp_rn(s);

        __stcs(out + base,       quant_vec(v0, inv_s, s));
        __stcs(out + base + 256, quant_vec(v1, inv_s, s));
        __stcs(out + base + 512, quant_vec(v2, inv_s, s));
        __stcs(out + base + 768, quant_vec(v3, inv_s, s));
    }
}

extern "C" void kernel_launch(void* const* d_in, const int* in_sizes, int n_in,
                              void* d_out, int out_size) {
    const float4* x     = (const float4*)d_in[0];   // 4096*4096 fp32
    const float*  scale = (const float*) d_in[1];   // 4096 fp32
    // d_in[2] = code (fixed FP4 codebook) — implemented via bit-trick rounding
    float4* out = (float4*)d_out;

    quantizer_fp4_kernel<<<PERSIST_BLOCKS, 256>>>(x, scale, out);
}

// round 13
// speedup vs baseline: 1.1278x; 1.0119x over previous
#include <cuda_runtime.h>
#include <cuda_bf16.h>
#include <cstdint>

// FP4 codebook magnitudes {0, 0.5, 1, 1.5, 2, 3, 4, 6} == e2m1.
// RN-to-1-mantissa-bit via integer round for |q| in [0.875, 8):
//   rb = (bits + 0x00200000) & 0x7fc00000
// fmin(.,6) clamps top, fmax(.,1) fixes [0.75,0.875), two selects handle
// thresholds 0.25 / 0.75. Exact midpoints: measure zero (rel_err was 0.0).
__device__ __forceinline__ float quant_one(float x, float inv_s, float s) {
    float q = x * inv_s;
    unsigned u = __float_as_uint(q);
    unsigned rb = (u + 0x00200000u) & 0x7fc00000u;
    float r = fminf(__uint_as_float(rb), 6.0f);
    r = fmaxf(r, 1.0f);
    r = (fabsf(q) < 0.75f) ? 0.5f : r;
    r = (fabsf(q) < 0.25f) ? 0.0f : r;
    float m = __uint_as_float(__float_as_uint(r) | (u & 0x80000000u));
    return m * s;
}

__device__ __forceinline__ float4 quant_vec(float4 v, float inv_s, float s) {
    float4 r;
    r.x = quant_one(v.x, inv_s, s);
    r.y = quant_one(v.y, inv_s, s);
    r.z = quant_one(v.z, inv_s, s);
    r.w = quant_one(v.w, inv_s, s);
    return r;
}

// R13: persistent single wave (1184 = 148 SMs x 8 CTAs) + fine-grain units +
// 2-stage software pipeline.
//  - Work unit = half row (512 float4, 2 per thread): 8192 units / 1184
//    blocks = 6.92 -> tail imbalance ~1.2% (vs 13.5% at row granularity).
//  - Next unit's 2 LDG.128 + scale issue BEFORE current unit's compute+store,
//    so loads stay continuously in flight at R4-level register cost.
#define NBLK   1184u
#define NUNITS 8192u   // 4096 rows x 2 half-rows

__global__ void __launch_bounds__(256) quantizer_fp4_kernel(
    const float4* __restrict__ x,
    const float*  __restrict__ scale,
    float4*       __restrict__ out)
{
    const unsigned tid = threadIdx.x;

    unsigned u = blockIdx.x;
    unsigned cbase = u * 512u + tid;

    // Prologue: load unit u
    float4 c0 = x[cbase];
    float4 c1 = x[cbase + 256];
    float  cs = __ldg(scale + (u >> 1));

    while (true) {
        const unsigned nu = u + NBLK;
        const bool more = (nu < NUNITS);

        // Prefetch next unit (front-batched, independent of current compute)
        float4 n0, n1;
        float  ns;
        unsigned nbase = nu * 512u + tid;
        if (more) {
            n0 = x[nbase];
            n1 = x[nbase + 256];
            ns = __ldg(scale + (nu >> 1));
        }

        // Compute + store current unit
        const float inv = __frcp_rn(cs);
        __stcs(out + cbase,       quant_vec(c0, inv, cs));
        __stcs(out + cbase + 256, quant_vec(c1, inv, cs));

        if (!more) break;
        u = nu; cbase = nbase; c0 = n0; c1 = n1; cs = ns;
    }
}

extern "C" void kernel_launch(void* const* d_in, const int* in_sizes, int n_in,
                              void* d_out, int out_size) {
    const float4* x     = (const float4*)d_in[0];   // 4096*4096 fp32
    const float*  scale = (const float*) d_in[1];   // 4096 fp32
    // d_in[2] = code (fixed FP4 codebook) — implemented via bit-trick rounding
    float4* out = (float4*)d_out;

    quantizer_fp4_kernel<<<NBLK, 256>>>(x, scale, out);
}